// round 4
// baseline (speedup 1.0000x reference)
#include <cuda_runtime.h>
#include <cuda_bf16.h>
#include <math.h>

// ---------------------------------------------------------------------------
// Seq2Seq LSTM (B=64, S=1024, T=512, H=512, D_IN=D_OUT=32), fp32.
// Persistent kernel: 128 CTAs x 256 threads, software grid barrier.
// Decoder feedback GEMM folded into precomputed M = dec_Wih0 @ out_W.
// ---------------------------------------------------------------------------

#define NB   128          // CTAs (<= 148 SMs -> all co-resident)
#define NT   256
#define B_    64
#define H_    512
#define G4    2048
#define DIN   32
#define DOUT  32
#define SLEN  1024
#define TLEN  512
#define SH_STRIDE 132     // 128 + 4 pad: conflict-free, 16B aligned

struct P {
    const float *src;
    const float *eWih0, *eWhh0, *ebih0, *ebhh0;
    const float *eWih1, *eWhh1, *ebih1, *ebhh1;
    const float *dWih0, *dWhh0, *dbih0, *dbhh0;
    const float *dWih1, *dWhh1, *dbih1, *dbhh1;
    const float *outW, *outB;
    float *out;
};

// ---- persistent state (device globals; allocation-free scratch) ----
__device__ float gH0[2][B_ * H_];
__device__ float gH1[2][B_ * H_];
__device__ float gC0[B_ * H_];
__device__ float gC1[B_ * H_];
__device__ float gM[G4 * H_];      // dec_Wih0 @ out_W   [2048 x 512]
__device__ float gB2[G4];          // dec_Wih0 @ out_b
__device__ unsigned g_count = 0;
__device__ volatile unsigned g_gen = 0;

__device__ __forceinline__ void grid_bar() {
    __threadfence();
    __syncthreads();
    if (threadIdx.x == 0) {
        unsigned gen = g_gen;
        unsigned t = atomicAdd(&g_count, 1u);
        if (t == (unsigned)(NB - 1)) {
            atomicExch(&g_count, 0u);
            __threadfence();
            g_gen = gen + 1u;
        } else {
            while (g_gen == gen) { __nanosleep(64); }
        }
    }
    __syncthreads();
}

__device__ __forceinline__ float sigm(float x) { return 1.0f / (1.0f + expf(-x)); }

// Accumulate gates += x @ W.T restricted to this thread's (gate,unit) row r.
// x: [64 x K] with row stride ld; W: [2048 x K] row-major.
// cg=true -> x is mutable cross-CTA state (bypass L1 with .cg).
__device__ __forceinline__ void accum_term(
    const float* __restrict__ x, int ld,
    const float* __restrict__ W, int K, bool cg,
    int r, int bhalf, int bq, float acc[4], float* sh)
{
    const int tid = threadIdx.x;
    for (int k0 = 0; k0 < K; k0 += 128) {
        const int kc  = (K - k0 < 128) ? (K - k0) : 128;
        const int kcq = kc >> 2;                       // float4 per row (32 or 8)
        const int lsh = (kcq == 32) ? 5 : 3;
        const int nf4 = kcq << 6;                      // 64 * kcq
        for (int idx = tid; idx < nf4; idx += NT) {
            int b  = idx >> lsh;
            int kq = idx & (kcq - 1);
            const float4* gp = (const float4*)(x + b * ld + k0) + kq;
            float4 v = cg ? __ldcg(gp) : __ldg(gp);
            *(float4*)(sh + b * SH_STRIDE + (kq << 2)) = v;
        }
        __syncthreads();
        const float* wr = W + (long)r * K + k0;
        const float* hb = sh + ((bhalf << 5) + bq) * SH_STRIDE;
        for (int kk = 0; kk < kc; kk += 4) {
            float4 wv = __ldg((const float4*)(wr + kk));
            #pragma unroll
            for (int m = 0; m < 4; m++) {
                float4 hv = *(const float4*)(hb + m * (8 * SH_STRIDE) + kk);
                acc[m] = fmaf(wv.x, hv.x,
                         fmaf(wv.y, hv.y,
                         fmaf(wv.z, hv.z,
                         fmaf(wv.w, hv.w, acc[m]))));
            }
        }
        __syncthreads();
    }
}

// One LSTM layer step: gates = xA@WA.T + xB@WB.T + bih + bhh (+ b2);
// c,h updated in place / to hout. CTA covers units [4*blockIdx, 4*blockIdx+4).
__device__ __forceinline__ void lstm_phase(
    const float* xA, int ldA, const float* WA, int KA, bool cgA,
    const float* xB, int ldB, const float* WB, int KB, bool cgB,
    const float* __restrict__ bih, const float* __restrict__ bhh,
    const float* __restrict__ b2,
    float* __restrict__ cstate, float* __restrict__ hout, float* sh)
{
    const int tid   = threadIdx.x;
    const int warp  = tid >> 5, lane = tid & 31;
    const int bhalf = warp >> 2, uloc = warp & 3;
    const int gate  = lane & 3,  bq   = lane >> 2;
    const int u = (blockIdx.x << 2) + uloc;
    const int r = (gate << 9) + u;             // gate*512 + unit  (i,f,g,o order)

    float base = __ldg(bih + r) + __ldg(bhh + r);
    if (b2) base += __ldg(b2 + r);
    float acc[4] = {base, base, base, base};

    if (KA) accum_term(xA, ldA, WA, KA, cgA, r, bhalf, bq, acc, sh);
    if (KB) accum_term(xB, ldB, WB, KB, cgB, r, bhalf, bq, acc, sh);

    const int srcbase = lane & ~3;
    #pragma unroll
    for (int m = 0; m < 4; m++) {
        float gi = __shfl_sync(0xffffffffu, acc[m], srcbase + 0);
        float gf = __shfl_sync(0xffffffffu, acc[m], srcbase + 1);
        float gg = __shfl_sync(0xffffffffu, acc[m], srcbase + 2);
        float go = __shfl_sync(0xffffffffu, acc[m], srcbase + 3);
        if (gate == 0) {
            int b   = (bhalf << 5) + bq + (m << 3);
            int idx = (b << 9) + u;
            float cp = __ldcg(cstate + idx);
            float cn = sigm(gf) * cp + sigm(gi) * tanhf(gg);
            __stcg(cstate + idx, cn);
            __stcg(hout + idx, sigm(go) * tanhf(cn));
        }
    }
}

// pred(t) = h1 @ out_W.T + out_b -> d_out[:, t, :]. CTAs 0..31 only.
__device__ __forceinline__ void do_pred(const P& p, const float* __restrict__ h1, int t)
{
    int g = blockIdx.x * NT + threadIdx.x;     // 0..8191
    int oid = g >> 2, part = g & 3;            // 2048 outputs, K split by 4
    int b = oid >> 5, j = oid & 31;
    const float* hr = h1 + (b << 9) + (part << 7);
    const float* wr = p.outW + (j << 9) + (part << 7);
    float s = 0.0f;
    #pragma unroll
    for (int k = 0; k < 128; k += 4) {
        float4 hv = __ldcg((const float4*)(hr + k));
        float4 wv = __ldg ((const float4*)(wr + k));
        s = fmaf(hv.x, wv.x, fmaf(hv.y, wv.y, fmaf(hv.z, wv.z, fmaf(hv.w, wv.w, s))));
    }
    s += __shfl_xor_sync(0xffffffffu, s, 1);
    s += __shfl_xor_sync(0xffffffffu, s, 2);
    if (part == 0)
        p.out[((long)b << 14) + (t << 5) + j] = s + __ldg(p.outB + j);
}

__global__ void __launch_bounds__(NT, 1) seq2seq_kernel(P p)
{
    __shared__ float sh[B_ * SH_STRIDE];
    const int gt = blockIdx.x * NT + threadIdx.x;   // 0..32767 (== 64*512)

    // ---- zero init of states (every run; d_out poisoned by harness) ----
    __stcg(&gH0[0][gt], 0.0f);
    __stcg(&gH1[0][gt], 0.0f);
    __stcg(&gC0[gt],    0.0f);
    __stcg(&gC1[gt],    0.0f);
    grid_bar();

    // ---- precompute M = dec_Wih0 @ out_W, b2 = dec_Wih0 @ out_b ----
    for (int o = gt; o < G4 * H_; o += NB * NT) {
        int rr = o >> 9, hc = o & 511;
        const float* wr = p.dWih0 + rr * DIN;
        const float* oc = p.outW + hc;
        float s = 0.0f;
        #pragma unroll
        for (int j = 0; j < DIN; j++) s = fmaf(__ldg(wr + j), __ldg(oc + j * H_), s);
        __stcg(&gM[o], s);
    }
    if (gt < G4) {
        const float* wr = p.dWih0 + gt * DIN;
        float s = 0.0f;
        #pragma unroll
        for (int j = 0; j < DIN; j++) s = fmaf(__ldg(wr + j), __ldg(p.outB + j), s);
        __stcg(&gB2[gt], s);
    }
    grid_bar();

    // ---- encoder: 1024 steps x 2 layers ----
    for (int t = 0; t < SLEN; t++) {
        const int rp = t & 1, wp = 1 - rp;
        lstm_phase(p.src + t * DIN, SLEN * DIN, p.eWih0, DIN, false,
                   gH0[rp], H_, p.eWhh0, H_, true,
                   p.ebih0, p.ebhh0, nullptr, gC0, gH0[wp], sh);
        grid_bar();
        lstm_phase(gH0[wp], H_, p.eWih1, H_, true,
                   gH1[rp], H_, p.eWhh1, H_, true,
                   p.ebih1, p.ebhh1, nullptr, gC1, gH1[wp], sh);
        grid_bar();
    }

    // ---- decoder: 512 steps x 2 layers (+ pred side job) ----
    // gates_L0(t) = h1(t-1)@M.T + h0(t-1)@dWhh0.T + bias + b2   (t>0)
    for (int t = 0; t < TLEN; t++) {
        const int rp = t & 1, wp = 1 - rp;   // S even -> parity continues
        lstm_phase(t ? gH1[rp] : nullptr, H_, gM, t ? H_ : 0, true,
                   gH0[rp], H_, p.dWhh0, H_, true,
                   p.dbih0, p.dbhh0, t ? gB2 : nullptr, gC0, gH0[wp], sh);
        if (t > 0 && blockIdx.x < 32) do_pred(p, gH1[rp], t - 1);
        grid_bar();
        lstm_phase(gH0[wp], H_, p.dWih1, H_, true,
                   gH1[rp], H_, p.dWhh1, H_, true,
                   p.dbih1, p.dbhh1, nullptr, gC1, gH1[wp], sh);
        grid_bar();
    }
    // final pred for t = TLEN-1 (h1 ended in buffer parity TLEN&1 == 0)
    if (blockIdx.x < 32) do_pred(p, gH1[0], TLEN - 1);
}

extern "C" void kernel_launch(void* const* d_in, const int* in_sizes, int n_in,
                              void* d_out, int out_size)
{
    // target_length may or may not be passed as a size-1 scalar at index 1.
    const int o = (in_sizes[1] < 100) ? 1 : 0;   // enc_Wih0 has 65536 elems

    P p;
    p.src   = (const float*)d_in[0];
    p.eWih0 = (const float*)d_in[1 + o];
    p.eWhh0 = (const float*)d_in[2 + o];
    p.ebih0 = (const float*)d_in[3 + o];
    p.ebhh0 = (const float*)d_in[4 + o];
    p.eWih1 = (const float*)d_in[5 + o];
    p.eWhh1 = (const float*)d_in[6 + o];
    p.ebih1 = (const float*)d_in[7 + o];
    p.ebhh1 = (const float*)d_in[8 + o];
    p.dWih0 = (const float*)d_in[9 + o];
    p.dWhh0 = (const float*)d_in[10 + o];
    p.dbih0 = (const float*)d_in[11 + o];
    p.dbhh0 = (const float*)d_in[12 + o];
    p.dWih1 = (const float*)d_in[13 + o];
    p.dWhh1 = (const float*)d_in[14 + o];
    p.dbih1 = (const float*)d_in[15 + o];
    p.dbhh1 = (const float*)d_in[16 + o];
    p.outW  = (const float*)d_in[17 + o];
    p.outB  = (const float*)d_in[18 + o];
    p.out   = (float*)d_out;

    seq2seq_kernel<<<NB, NT>>>(p);
}

// round 5
// speedup vs baseline: 1.6065x; 1.6065x over previous
#include <cuda_runtime.h>
#include <cuda_bf16.h>
#include <math.h>

// ---------------------------------------------------------------------------
// Seq2Seq LSTM (B=64, S=1024, T=512, H=512, D_IN=D_OUT=32), fp32.
// Persistent kernel: 128 CTAs x 512 threads, software grid barrier.
// Each CTA owns 16 gate-rows (4 units x 4 gates). 8 K-segments x 64 threads,
// register blocking 2 rows x 8 batches per thread, shared-mem reduction.
// Decoder feedback GEMM folded into precomputed M = dec_Wih0 @ out_W.
// ---------------------------------------------------------------------------

#define NB   128
#define NT   512
#define B_    64
#define H_    512
#define G4   2048
#define DIN   32
#define SLEN 1024
#define TLEN  512
#define CH     64                 // staged k-chunk per segment
#define CHS    68                 // chunk row stride (floats): conflict-free
#define BUFSZ  (64 * CHS)         // 4352 floats per segment buffer
#define REDS   65                 // reduction row stride (floats)
#define REDSEG 1040               // 16 rows * 65 per segment
#define SMEM_BYTES (8 * BUFSZ * 4)   // 139264 B

struct P {
    const float *src;
    const float *eWih0, *eWhh0, *ebih0, *ebhh0;
    const float *eWih1, *eWhh1, *ebih1, *ebhh1;
    const float *dWih0, *dWhh0, *dbih0, *dbhh0;
    const float *dWih1, *dWhh1, *dbih1, *dbhh1;
    const float *outW, *outB;
    float *out;
};

// ---- persistent state (device globals; allocation-free scratch) ----
__device__ float gH0[2][B_ * H_];
__device__ float gH1[2][B_ * H_];
__device__ float gC0[B_ * H_];
__device__ float gC1[B_ * H_];
__device__ float gM[G4 * H_];      // dec_Wih0 @ out_W   [2048 x 512]
__device__ float gB2[G4];          // dec_Wih0 @ out_b
__device__ unsigned g_count = 0;
__device__ volatile unsigned g_gen = 0;

__device__ __forceinline__ void grid_bar() {
    __threadfence();
    __syncthreads();
    if (threadIdx.x == 0) {
        unsigned gen = g_gen;
        unsigned t = atomicAdd(&g_count, 1u);
        if (t == (unsigned)(NB - 1)) {
            atomicExch(&g_count, 0u);
            __threadfence();
            g_gen = gen + 1u;
        } else {
            while (g_gen == gen) { __nanosleep(32); }
        }
    }
    __syncthreads();
}

__device__ __forceinline__ float sigm(float x) { return 1.0f / (1.0f + expf(-x)); }

__device__ __forceinline__ float fma4(float4 a, float4 b, float s) {
    return fmaf(a.x, b.x, fmaf(a.y, b.y, fmaf(a.z, b.z, fmaf(a.w, b.w, s))));
}

// Accumulate this thread's 2x8 partial gate outputs over its K-segment.
// x: [64 x K] rows with stride ld; W: [2048 x K] row-major.
__device__ __forceinline__ void term_acc(
    const float* __restrict__ x, int ld,
    const float* __restrict__ W, int K, bool cg,
    int seg, int segtid, int gate, int bq, int u0,
    float acc[2][8], float* smem)
{
    const int kseg  = K >> 3;            // k per segment (64 or 4)
    const int kbase = seg * kseg;
    float* buf = smem + seg * BUFSZ;
    const float* w0 = W + (long)((gate << 9) + u0) * K + kbase;
    const float* w1 = w0 + K;

    for (int c0 = 0; c0 < kseg; c0 += CH) {
        int kc = kseg - c0; if (kc > CH) kc = CH;     // 64 or 4
        const int kcq = kc >> 2;                      // 16 or 1
        const int nf4 = kcq << 6;
        // ---- stage x chunk into this segment's buffer (64 threads) ----
        for (int idx = segtid; idx < nf4; idx += 64) {
            int b, kq;
            if (kcq == 16) { b = idx >> 4; kq = idx & 15; }
            else           { b = idx;      kq = 0; }
            const float4* gp = (const float4*)(x + b * ld + kbase + c0) + kq;
            float4 v = cg ? __ldcg(gp) : __ldg(gp);
            *(float4*)(buf + b * CHS + (kq << 2)) = v;
        }
        __syncthreads();
        // ---- compute: 2 weight rows x 8 batches per thread ----
        #pragma unroll 4
        for (int kk = 0; kk < kc; kk += 4) {
            float4 wa = __ldg((const float4*)(w0 + c0 + kk));
            float4 wb = __ldg((const float4*)(w1 + c0 + kk));
            const float* hb = buf + bq * CHS + kk;
            #pragma unroll
            for (int m = 0; m < 8; m++) {
                float4 hv = *(const float4*)(hb + m * (8 * CHS));
                acc[0][m] = fma4(wa, hv, acc[0][m]);
                acc[1][m] = fma4(wb, hv, acc[1][m]);
            }
        }
        __syncthreads();
    }
}

// One LSTM layer step. CTA covers units [4*bid, 4*bid+4) x 4 gates.
__device__ __forceinline__ void lstm_phase(
    const float* xA, int ldA, const float* WA, int KA, bool cgA,
    const float* xB, int ldB, const float* WB, int KB, bool cgB,
    const float* __restrict__ bih, const float* __restrict__ bhh,
    const float* __restrict__ b2,
    float* __restrict__ cst, float* __restrict__ hout, float* smem)
{
    const int tid    = threadIdx.x;
    const int w      = tid >> 5, lane = tid & 31;
    const int seg    = w >> 1,   segw = w & 1;
    const int segtid = (segw << 5) | lane;
    const int gate   = lane & 3, bq = lane >> 2;
    const int u0     = (blockIdx.x << 2) + (segw << 1);   // units u0, u0+1

    float acc[2][8];
    #pragma unroll
    for (int i = 0; i < 2; i++)
        #pragma unroll
        for (int m = 0; m < 8; m++) acc[i][m] = 0.0f;

    if (KA) term_acc(xA, ldA, WA, KA, cgA, seg, segtid, gate, bq, u0, acc, smem);
    if (KB) term_acc(xB, ldB, WB, KB, cgB, seg, segtid, gate, bq, u0, acc, smem);
    // (trailing __syncthreads inside term_acc separates compute from stores)

    // ---- store partials: red[seg][gate*4+uloc][b] with stride-65 rows ----
    float* red = smem;
    #pragma unroll
    for (int uu = 0; uu < 2; uu++) {
        int rl = (gate << 2) + (segw << 1) + uu;
        #pragma unroll
        for (int m = 0; m < 8; m++)
            red[seg * REDSEG + rl * REDS + ((m << 3) + bq)] = acc[uu][m];
    }
    __syncthreads();

    // ---- finalize: 256 threads, one (b, u) each ----
    if (tid < 256) {
        const int u = tid & 3, b = tid >> 2;
        const int ug = (blockIdx.x << 2) + u;
        float g4v[4];
        #pragma unroll
        for (int g = 0; g < 4; g++) {
            float s = 0.0f;
            #pragma unroll
            for (int s8 = 0; s8 < 8; s8++)
                s += red[s8 * REDSEG + ((g << 2) + u) * REDS + b];
            int r = (g << 9) + ug;
            s += __ldg(bih + r) + __ldg(bhh + r);
            if (b2) s += __ldg(b2 + r);
            g4v[g] = s;
        }
        const int idx = (b << 9) + ug;
        float cp = __ldcg(cst + idx);
        float cn = sigm(g4v[1]) * cp + sigm(g4v[0]) * tanhf(g4v[2]);
        __stcg(cst + idx, cn);
        __stcg(hout + idx, sigm(g4v[3]) * tanhf(cn));
    }
}

// pred(t) = h1 @ out_W.T + out_b -> d_out[:, t, :]. CTAs 0..15 only.
__device__ __forceinline__ void do_pred(const P& p, const float* __restrict__ h1, int t)
{
    int g = blockIdx.x * NT + threadIdx.x;     // 0..8191
    int oid = g >> 2, part = g & 3;            // 2048 outputs, K split by 4
    int b = oid >> 5, j = oid & 31;
    const float* hr = h1 + (b << 9) + (part << 7);
    const float* wr = p.outW + (j << 9) + (part << 7);
    float s = 0.0f;
    #pragma unroll
    for (int k = 0; k < 128; k += 4) {
        float4 hv = __ldcg((const float4*)(hr + k));
        float4 wv = __ldg ((const float4*)(wr + k));
        s = fmaf(hv.x, wv.x, fmaf(hv.y, wv.y, fmaf(hv.z, wv.z, fmaf(hv.w, wv.w, s))));
    }
    s += __shfl_xor_sync(0xffffffffu, s, 1);
    s += __shfl_xor_sync(0xffffffffu, s, 2);
    if (part == 0)
        p.out[((long)b << 14) + (t << 5) + j] = s + __ldg(p.outB + j);
}

__global__ void __launch_bounds__(NT, 1) seq2seq_kernel(P p)
{
    extern __shared__ float smem[];
    const int gt = blockIdx.x * NT + threadIdx.x;   // 0..65535

    // ---- zero init of states ----
    if (gt < B_ * H_) {
        __stcg(&gH0[0][gt], 0.0f);
        __stcg(&gH1[0][gt], 0.0f);
        __stcg(&gC0[gt],    0.0f);
        __stcg(&gC1[gt],    0.0f);
    }
    grid_bar();

    // ---- precompute M = dec_Wih0 @ out_W, b2 = dec_Wih0 @ out_b ----
    for (int o = gt; o < G4 * H_; o += NB * NT) {
        int rr = o >> 9, hc = o & 511;
        const float* wr = p.dWih0 + rr * DIN;
        const float* oc = p.outW + hc;
        float s = 0.0f;
        #pragma unroll
        for (int j = 0; j < DIN; j++) s = fmaf(__ldg(wr + j), __ldg(oc + j * H_), s);
        __stcg(&gM[o], s);
    }
    if (gt < G4) {
        const float* wr = p.dWih0 + gt * DIN;
        float s = 0.0f;
        #pragma unroll
        for (int j = 0; j < DIN; j++) s = fmaf(__ldg(wr + j), __ldg(p.outB + j), s);
        __stcg(&gB2[gt], s);
    }
    grid_bar();

    // ---- encoder: 1024 steps x 2 layers ----
    for (int t = 0; t < SLEN; t++) {
        const int rp = t & 1, wp = 1 - rp;
        lstm_phase(p.src + t * DIN, SLEN * DIN, p.eWih0, DIN, false,
                   gH0[rp], H_, p.eWhh0, H_, true,
                   p.ebih0, p.ebhh0, nullptr, gC0, gH0[wp], smem);
        grid_bar();
        lstm_phase(gH0[wp], H_, p.eWih1, H_, true,
                   gH1[rp], H_, p.eWhh1, H_, true,
                   p.ebih1, p.ebhh1, nullptr, gC1, gH1[wp], smem);
        grid_bar();
    }

    // ---- decoder: 512 steps x 2 layers (+ pred side job) ----
    for (int t = 0; t < TLEN; t++) {
        const int rp = t & 1, wp = 1 - rp;
        lstm_phase(t ? gH1[rp] : nullptr, H_, gM, t ? H_ : 0, true,
                   gH0[rp], H_, p.dWhh0, H_, true,
                   p.dbih0, p.dbhh0, t ? gB2 : nullptr, gC0, gH0[wp], smem);
        if (t > 0 && blockIdx.x < 16) do_pred(p, gH1[rp], t - 1);
        grid_bar();
        lstm_phase(gH0[wp], H_, p.dWih1, H_, true,
                   gH1[rp], H_, p.dWhh1, H_, true,
                   p.dbih1, p.dbhh1, nullptr, gC1, gH1[wp], smem);
        grid_bar();
    }
    // final pred for t = TLEN-1 (h1 parity ends at buffer 0)
    if (blockIdx.x < 16) do_pred(p, gH1[0], TLEN - 1);
}

extern "C" void kernel_launch(void* const* d_in, const int* in_sizes, int n_in,
                              void* d_out, int out_size)
{
    const int o = (in_sizes[1] < 100) ? 1 : 0;   // skip target_length scalar if present

    P p;
    p.src   = (const float*)d_in[0];
    p.eWih0 = (const float*)d_in[1 + o];
    p.eWhh0 = (const float*)d_in[2 + o];
    p.ebih0 = (const float*)d_in[3 + o];
    p.ebhh0 = (const float*)d_in[4 + o];
    p.eWih1 = (const float*)d_in[5 + o];
    p.eWhh1 = (const float*)d_in[6 + o];
    p.ebih1 = (const float*)d_in[7 + o];
    p.ebhh1 = (const float*)d_in[8 + o];
    p.dWih0 = (const float*)d_in[9 + o];
    p.dWhh0 = (const float*)d_in[10 + o];
    p.dbih0 = (const float*)d_in[11 + o];
    p.dbhh0 = (const float*)d_in[12 + o];
    p.dWih1 = (const float*)d_in[13 + o];
    p.dWhh1 = (const float*)d_in[14 + o];
    p.dbih1 = (const float*)d_in[15 + o];
    p.dbhh1 = (const float*)d_in[16 + o];
    p.outW  = (const float*)d_in[17 + o];
    p.outB  = (const float*)d_in[18 + o];
    p.out   = (float*)d_out;

    cudaFuncSetAttribute(seq2seq_kernel,
                         cudaFuncAttributeMaxDynamicSharedMemorySize, SMEM_BYTES);
    seq2seq_kernel<<<NB, NT, SMEM_BYTES>>>(p);
}

// round 6
// speedup vs baseline: 1.8973x; 1.1810x over previous
#include <cuda_runtime.h>
#include <cuda_bf16.h>
#include <math.h>

// ---------------------------------------------------------------------------
// Seq2Seq LSTM (B=64, S=1024, T=512, H=512, D_IN=D_OUT=32), fp32.
// Persistent kernel: 128 CTAs x 512 threads, flag-based grid barrier.
// Each CTA owns 16 gate-rows (4 units x 4 gates) x 64 batches.
// One warp covers the full 16x64 tile over a K-segment (K/16 per warp),
// register blocking 4 rows x 8 batches, warp-private staging + reg prefetch.
// Decoder feedback GEMM folded into precomputed M = dec_Wih0 @ out_W.
// ---------------------------------------------------------------------------

#define NB   128
#define NT   512
#define B_    64
#define H_    512
#define G4   2048
#define DIN   32
#define SLEN 1024
#define TLEN  512

#define BUFW 12                      // floats per batch row in stage buffer
#define BUFSZ (64 * BUFW)            // 768 floats per warp
#define REDBASE (16 * BUFSZ)         // 12288 floats
#define RROW 1042                    // reduction row stride (floats)
#define SMEM_FLOATS (REDBASE + 16 * RROW)
#define SMEM_BYTES  (SMEM_FLOATS * 4)   // 115840 B

struct P {
    const float *src;
    const float *eWih0, *eWhh0, *ebih0, *ebhh0;
    const float *eWih1, *eWhh1, *ebih1, *ebhh1;
    const float *dWih0, *dWhh0, *dbih0, *dbhh0;
    const float *dWih1, *dWhh1, *dbih1, *dbhh1;
    const float *outW, *outB;
    float *out;
};

// ---- persistent state (device globals; allocation-free scratch) ----
__device__ float gH0[2][B_ * H_];
__device__ float gH1[2][B_ * H_];
__device__ float gC0[B_ * H_];
__device__ float gC1[B_ * H_];
__device__ float gM[G4 * H_];      // dec_Wih0 @ out_W   [2048 x 512]
__device__ float gB2[G4];          // dec_Wih0 @ out_b
__device__ unsigned gFlag[NB];     // monotonic per-CTA arrival counters
__device__ volatile unsigned g_gen = 0;

// Flag-based grid barrier: no atomic contention. CTA0's first 128 threads
// poll the 127 per-CTA flags in parallel, then thread0 bumps g_gen.
__device__ __forceinline__ void grid_bar(unsigned &bgen) {
    __threadfence();
    __syncthreads();
    bgen++;
    if (blockIdx.x == 0) {
        if (threadIdx.x > 0 && threadIdx.x < NB) {
            volatile unsigned* f = gFlag + threadIdx.x;
            while (*f < bgen) __nanosleep(32);
        }
        __syncthreads();
        if (threadIdx.x == 0) { __threadfence(); g_gen = bgen; }
    } else {
        if (threadIdx.x == 0) {
            ((volatile unsigned*)gFlag)[blockIdx.x] = bgen;
            while (g_gen < bgen) __nanosleep(32);
        }
        __syncthreads();
    }
}

__device__ __forceinline__ float sigm(float x) { return 1.0f / (1.0f + expf(-x)); }

__device__ __forceinline__ float fma4(float4 a, float4 b, float s) {
    return fmaf(a.x, b.x, fmaf(a.y, b.y, fmaf(a.z, b.z, fmaf(a.w, b.w, s))));
}

// K=512 term: this warp (= segment `seg`) accumulates its 32-k slice into
// acc[4 rows][8 batches]. Wrow0 = W + (gate*512 + 4*bid)*512 (rr stride 512).
// x: [64 rows, stride ld]. 4 chunks of 8 k, register-prefetched.
__device__ __forceinline__ void term512(
    const float* __restrict__ x, int ld, const float* __restrict__ Wrow0,
    bool cg, int seg, int lane, int bq, float acc[4][8], float* buf)
{
    const int kbase = seg * 32;
    const int j0 = lane, j1 = 32 + lane, j2 = 64 + lane, j3 = 96 + lane;
    const int b0 = j0 >> 1, b1 = j1 >> 1, b2_ = j2 >> 1, b3 = j3 >> 1;
    const int q0 = (j0 & 1) << 2, q1 = (j1 & 1) << 2, q2 = (j2 & 1) << 2, q3 = (j3 & 1) << 2;

    float4 pf0, pf1, pf2, pf3;
    {
        const float* g0 = x + b0 * ld + kbase + q0;
        const float* g1 = x + b1 * ld + kbase + q1;
        const float* g2 = x + b2_ * ld + kbase + q2;
        const float* g3 = x + b3 * ld + kbase + q3;
        if (cg) { pf0 = __ldcg((const float4*)g0); pf1 = __ldcg((const float4*)g1);
                  pf2 = __ldcg((const float4*)g2); pf3 = __ldcg((const float4*)g3); }
        else    { pf0 = __ldg((const float4*)g0);  pf1 = __ldg((const float4*)g1);
                  pf2 = __ldg((const float4*)g2);  pf3 = __ldg((const float4*)g3); }
    }
    #pragma unroll
    for (int c = 0; c < 4; c++) {
        __syncwarp();                      // prior chunk fully consumed
        *(float4*)(buf + b0 * BUFW + q0) = pf0;
        *(float4*)(buf + b1 * BUFW + q1) = pf1;
        *(float4*)(buf + b2_ * BUFW + q2) = pf2;
        *(float4*)(buf + b3 * BUFW + q3) = pf3;
        if (c < 3) {                       // prefetch next chunk (hidden by compute)
            const int ko = kbase + (c + 1) * 8;
            const float* g0 = x + b0 * ld + ko + q0;
            const float* g1 = x + b1 * ld + ko + q1;
            const float* g2 = x + b2_ * ld + ko + q2;
            const float* g3 = x + b3 * ld + ko + q3;
            if (cg) { pf0 = __ldcg((const float4*)g0); pf1 = __ldcg((const float4*)g1);
                      pf2 = __ldcg((const float4*)g2); pf3 = __ldcg((const float4*)g3); }
            else    { pf0 = __ldg((const float4*)g0);  pf1 = __ldg((const float4*)g1);
                      pf2 = __ldg((const float4*)g2);  pf3 = __ldg((const float4*)g3); }
        }
        __syncwarp();                      // staged data visible
        const float* wb = Wrow0 + kbase + c * 8;
        #pragma unroll
        for (int kk = 0; kk < 8; kk += 4) {
            float4 wv0 = __ldg((const float4*)(wb + 0 * H_ + kk));
            float4 wv1 = __ldg((const float4*)(wb + 1 * H_ + kk));
            float4 wv2 = __ldg((const float4*)(wb + 2 * H_ + kk));
            float4 wv3 = __ldg((const float4*)(wb + 3 * H_ + kk));
            const float* hb = buf + bq * BUFW + kk;
            #pragma unroll
            for (int m = 0; m < 8; m++) {
                float4 hv = *(const float4*)(hb + m * (8 * BUFW));
                acc[0][m] = fma4(wv0, hv, acc[0][m]);
                acc[1][m] = fma4(wv1, hv, acc[1][m]);
                acc[2][m] = fma4(wv2, hv, acc[2][m]);
                acc[3][m] = fma4(wv3, hv, acc[3][m]);
            }
        }
    }
    __syncwarp();
}

// K=32 term (encoder L0 input): each warp takes 2 k columns.
// Wrow0 = W + (gate*512 + 4*bid)*32 (rr stride 32).
__device__ __forceinline__ void term32(
    const float* __restrict__ x, int ld, const float* __restrict__ Wrow0,
    int seg, int lane, int bq, float acc[4][8], float* buf)
{
    const int kbase = seg * 2;
    __syncwarp();
    #pragma unroll
    for (int i = 0; i < 2; i++) {
        int b = lane + (i << 5);
        float2 v = __ldg((const float2*)(x + b * ld + kbase));
        *(float2*)(buf + b * BUFW) = v;
    }
    __syncwarp();
    float2 w0 = __ldg((const float2*)(Wrow0 + 0 * DIN + kbase));
    float2 w1 = __ldg((const float2*)(Wrow0 + 1 * DIN + kbase));
    float2 w2 = __ldg((const float2*)(Wrow0 + 2 * DIN + kbase));
    float2 w3 = __ldg((const float2*)(Wrow0 + 3 * DIN + kbase));
    #pragma unroll
    for (int m = 0; m < 8; m++) {
        float2 hv = *(const float2*)(buf + ((m << 3) + bq) * BUFW);
        acc[0][m] = fmaf(w0.x, hv.x, fmaf(w0.y, hv.y, acc[0][m]));
        acc[1][m] = fmaf(w1.x, hv.x, fmaf(w1.y, hv.y, acc[1][m]));
        acc[2][m] = fmaf(w2.x, hv.x, fmaf(w2.y, hv.y, acc[2][m]));
        acc[3][m] = fmaf(w3.x, hv.x, fmaf(w3.y, hv.y, acc[3][m]));
    }
    __syncwarp();
}

// One LSTM layer step. CTA covers units [4*bid, 4*bid+4) x 4 gates.
// Term A: KA in {0, 32, 512}; term B always K=512 (h-state, .cg).
__device__ __forceinline__ void lstm_phase(
    const float* xA, int ldA, const float* __restrict__ WA, int KA, bool cgA,
    const float* xB, const float* __restrict__ WB,
    const float* __restrict__ bih, const float* __restrict__ bhh,
    const float* __restrict__ b2,
    float* __restrict__ cst, float* __restrict__ hout, float* smem)
{
    const int tid  = threadIdx.x;
    const int w    = tid >> 5, lane = tid & 31;
    const int gate = lane >> 3, bq = lane & 7;
    float* buf = smem + w * BUFSZ;
    float* red = smem + REDBASE;

    float acc[4][8];
    #pragma unroll
    for (int r = 0; r < 4; r++)
        #pragma unroll
        for (int m = 0; m < 8; m++) acc[r][m] = 0.0f;

    const size_t rowbase = (size_t)((gate << 9) + (blockIdx.x << 2));
    if (KA == 512)     term512(xA, ldA, WA + rowbase * H_,  cgA, w, lane, bq, acc, buf);
    else if (KA == 32) term32 (xA, ldA, WA + rowbase * DIN,       w, lane, bq, acc, buf);
    term512(xB, H_, WB + rowbase * H_, true, w, lane, bq, acc, buf);

    // ---- partial store: red[row16][seg16*64 + b] ----
    #pragma unroll
    for (int rr = 0; rr < 4; rr++)
        #pragma unroll
        for (int m = 0; m < 8; m++)
            red[((gate << 2) + rr) * RROW + (w << 6) + (m << 3) + bq] = acc[rr][m];
    __syncthreads();

    // ---- finalize: 256 threads, one (b, u) each ----
    if (tid < 256) {
        const int u = tid & 3, b = tid >> 2;
        const int ug = (blockIdx.x << 2) + u;
        float g4v[4];
        #pragma unroll
        for (int g = 0; g < 4; g++) {
            float s = 0.0f;
            #pragma unroll
            for (int s16 = 0; s16 < 16; s16++)
                s += red[((g << 2) + u) * RROW + (s16 << 6) + b];
            int r = (g << 9) + ug;
            s += __ldg(bih + r) + __ldg(bhh + r);
            if (b2) s += __ldg(b2 + r);
            g4v[g] = s;
        }
        const int idx = (b << 9) + ug;
        float cp = __ldcg(cst + idx);
        float cn = sigm(g4v[1]) * cp + sigm(g4v[0]) * tanhf(g4v[2]);
        __stcg(cst + idx, cn);
        __stcg(hout + idx, sigm(g4v[3]) * tanhf(cn));
    }
}

// pred(t) = h1 @ out_W.T + out_b -> d_out[:, t, :]. CTAs 0..15 only.
__device__ __forceinline__ void do_pred(const P& p, const float* __restrict__ h1, int t)
{
    int g = blockIdx.x * NT + threadIdx.x;     // 0..8191
    int oid = g >> 2, part = g & 3;            // 2048 outputs, K split by 4
    int b = oid >> 5, j = oid & 31;
    const float* hr = h1 + (b << 9) + (part << 7);
    const float* wr = p.outW + (j << 9) + (part << 7);
    float s = 0.0f;
    #pragma unroll
    for (int k = 0; k < 128; k += 4) {
        float4 hv = __ldcg((const float4*)(hr + k));
        float4 wv = __ldg ((const float4*)(wr + k));
        s = fmaf(hv.x, wv.x, fmaf(hv.y, wv.y, fmaf(hv.z, wv.z, fmaf(hv.w, wv.w, s))));
    }
    s += __shfl_xor_sync(0xffffffffu, s, 1);
    s += __shfl_xor_sync(0xffffffffu, s, 2);
    if (part == 0)
        p.out[((long)b << 14) + (t << 5) + j] = s + __ldg(p.outB + j);
}

__global__ void __launch_bounds__(NT, 1) seq2seq_kernel(P p)
{
    extern __shared__ float smem[];
    const int gt = blockIdx.x * NT + threadIdx.x;   // 0..65535
    unsigned bgen = g_gen;                          // monotonic barrier epoch

    // ---- zero init of states ----
    if (gt < B_ * H_) {
        __stcg(&gH0[0][gt], 0.0f);
        __stcg(&gH1[0][gt], 0.0f);
        __stcg(&gC0[gt],    0.0f);
        __stcg(&gC1[gt],    0.0f);
    }
    grid_bar(bgen);

    // ---- precompute M = dec_Wih0 @ out_W, b2 = dec_Wih0 @ out_b ----
    for (int o = gt; o < G4 * H_; o += NB * NT) {
        int rr = o >> 9, hc = o & 511;
        const float* wr = p.dWih0 + rr * DIN;
        const float* oc = p.outW + hc;
        float s = 0.0f;
        #pragma unroll
        for (int j = 0; j < DIN; j++) s = fmaf(__ldg(wr + j), __ldg(oc + j * H_), s);
        __stcg(&gM[o], s);
    }
    if (gt < G4) {
        const float* wr = p.dWih0 + gt * DIN;
        float s = 0.0f;
        #pragma unroll
        for (int j = 0; j < DIN; j++) s = fmaf(__ldg(wr + j), __ldg(p.outB + j), s);
        __stcg(&gB2[gt], s);
    }
    grid_bar(bgen);

    // ---- encoder: 1024 steps x 2 layers ----
    for (int t = 0; t < SLEN; t++) {
        const int rp = t & 1, wp = 1 - rp;
        lstm_phase(p.src + t * DIN, SLEN * DIN, p.eWih0, DIN, false,
                   gH0[rp], p.eWhh0,
                   p.ebih0, p.ebhh0, nullptr, gC0, gH0[wp], smem);
        grid_bar(bgen);
        lstm_phase(gH0[wp], H_, p.eWih1, H_, true,
                   gH1[rp], p.eWhh1,
                   p.ebih1, p.ebhh1, nullptr, gC1, gH1[wp], smem);
        grid_bar(bgen);
    }

    // ---- decoder: 512 steps x 2 layers (+ pred side job) ----
    for (int t = 0; t < TLEN; t++) {
        const int rp = t & 1, wp = 1 - rp;
        lstm_phase(t ? gH1[rp] : nullptr, H_, gM, t ? H_ : 0, true,
                   gH0[rp], p.dWhh0,
                   p.dbih0, p.dbhh0, t ? gB2 : nullptr, gC0, gH0[wp], smem);
        if (t > 0 && blockIdx.x < 16) do_pred(p, gH1[rp], t - 1);
        grid_bar(bgen);
        lstm_phase(gH0[wp], H_, p.dWih1, H_, true,
                   gH1[rp], p.dWhh1,
                   p.dbih1, p.dbhh1, nullptr, gC1, gH1[wp], smem);
        grid_bar(bgen);
    }
    // final pred for t = TLEN-1 (h1 parity ends at buffer 0)
    if (blockIdx.x < 16) do_pred(p, gH1[0], TLEN - 1);
}

extern "C" void kernel_launch(void* const* d_in, const int* in_sizes, int n_in,
                              void* d_out, int out_size)
{
    const int o = (in_sizes[1] < 100) ? 1 : 0;   // skip target_length scalar if present

    P p;
    p.src   = (const float*)d_in[0];
    p.eWih0 = (const float*)d_in[1 + o];
    p.eWhh0 = (const float*)d_in[2 + o];
    p.ebih0 = (const float*)d_in[3 + o];
    p.ebhh0 = (const float*)d_in[4 + o];
    p.eWih1 = (const float*)d_in[5 + o];
    p.eWhh1 = (const float*)d_in[6 + o];
    p.ebih1 = (const float*)d_in[7 + o];
    p.ebhh1 = (const float*)d_in[8 + o];
    p.dWih0 = (const float*)d_in[9 + o];
    p.dWhh0 = (const float*)d_in[10 + o];
    p.dbih0 = (const float*)d_in[11 + o];
    p.dbhh0 = (const float*)d_in[12 + o];
    p.dWih1 = (const float*)d_in[13 + o];
    p.dWhh1 = (const float*)d_in[14 + o];
    p.dbih1 = (const float*)d_in[15 + o];
    p.dbhh1 = (const float*)d_in[16 + o];
    p.outW  = (const float*)d_in[17 + o];
    p.outB  = (const float*)d_in[18 + o];
    p.out   = (float*)d_out;

    cudaFuncSetAttribute(seq2seq_kernel,
                         cudaFuncAttributeMaxDynamicSharedMemorySize, SMEM_BYTES);
    seq2seq_kernel<<<NB, NT, SMEM_BYTES>>>(p);
}

// round 7
// speedup vs baseline: 2.1410x; 1.1284x over previous
#include <cuda_runtime.h>
#include <cuda_bf16.h>
#include <math.h>

// ---------------------------------------------------------------------------
// Seq2Seq LSTM (B=64, S=1024, T=512, H=512, D_IN=D_OUT=32), fp32.
// Persistent kernel: 128 CTAs x 512 threads, flag-based grid barrier.
// Each CTA owns 16 gate-rows (4 units x 4 gates) x 64 batches per layer-tile.
// Encoder: phases MERGED -> one barrier computes L1(t-1) AND L0(t)
//   (8 warps per layer-tile, 64-k slice per warp).
// Decoder: unmerged (serial dep), 16 warps x 32-k slice.
// h(t) lives in buffer t&1. Decoder feedback GEMM folded into gM.
// ---------------------------------------------------------------------------

#define NB   128
#define NT   512
#define B_    64
#define H_    512
#define G4   2048
#define DIN   32
#define SLEN 1024
#define TLEN  512

#define BUFW 12                       // floats per batch row in stage buffer
#define BUFSZ (64 * BUFW)             // 768 floats per warp
#define REDBASE (16 * BUFSZ)          // 12288 floats
#define RROW  1042                    // unmerged reduction row stride
#define RROW2 520                     // merged reduction row stride (bank-exact)
#define SMEM_FLOATS (REDBASE + 16 * RROW)     // >= REDBASE + 32*RROW2
#define SMEM_BYTES  (SMEM_FLOATS * 4)         // 115840 B

struct P {
    const float *src;
    const float *eWih0, *eWhh0, *ebih0, *ebhh0;
    const float *eWih1, *eWhh1, *ebih1, *ebhh1;
    const float *dWih0, *dWhh0, *dbih0, *dbhh0;
    const float *dWih1, *dWhh1, *dbih1, *dbhh1;
    const float *outW, *outB;
    float *out;
};

// ---- persistent state (device globals; allocation-free scratch) ----
__device__ float gH0[2][B_ * H_];
__device__ float gH1[2][B_ * H_];
__device__ float gC0[B_ * H_];
__device__ float gC1[B_ * H_];
__device__ float gM[G4 * H_];      // dec_Wih0 @ out_W   [2048 x 512]
__device__ float gB2[G4];          // dec_Wih0 @ out_b
__device__ unsigned gFlag[NB];     // monotonic per-CTA arrival counters
__device__ volatile unsigned g_gen = 0;

__device__ __forceinline__ void grid_bar(unsigned &bgen) {
    __threadfence();
    __syncthreads();
    bgen++;
    if (blockIdx.x == 0) {
        if (threadIdx.x > 0 && threadIdx.x < NB) {
            volatile unsigned* f = gFlag + threadIdx.x;
            while (*f < bgen) __nanosleep(32);
        }
        __syncthreads();
        if (threadIdx.x == 0) { __threadfence(); g_gen = bgen; }
    } else {
        if (threadIdx.x == 0) {
            ((volatile unsigned*)gFlag)[blockIdx.x] = bgen;
            while (g_gen < bgen) __nanosleep(32);
        }
        __syncthreads();
    }
}

__device__ __forceinline__ float sigm(float x) { return 1.0f / (1.0f + expf(-x)); }

__device__ __forceinline__ float fma4(float4 a, float4 b, float s) {
    return fmaf(a.x, b.x, fmaf(a.y, b.y, fmaf(a.z, b.z, fmaf(a.w, b.w, s))));
}

// K=512 term: warp accumulates nch chunks of 8 k starting at kbase into
// acc[4 rows][8 batches]. Wrow0 = W + rowbase*512 (row stride 512).
// x: [64 rows, stride ld]. Register-prefetched staging, warp-private buffer.
__device__ __forceinline__ void term512(
    const float* __restrict__ x, int ld, const float* __restrict__ Wrow0,
    bool cg, int kbase, int nch, int lane, int bq, float acc[4][8], float* buf)
{
    const int j0 = lane, j1 = 32 + lane, j2 = 64 + lane, j3 = 96 + lane;
    const int b0 = j0 >> 1, b1 = j1 >> 1, b2_ = j2 >> 1, b3 = j3 >> 1;
    const int q0 = (j0 & 1) << 2, q1 = (j1 & 1) << 2, q2 = (j2 & 1) << 2, q3 = (j3 & 1) << 2;

    float4 pf0, pf1, pf2, pf3;
    {
        const float* g0 = x + b0 * ld + kbase + q0;
        const float* g1 = x + b1 * ld + kbase + q1;
        const float* g2 = x + b2_ * ld + kbase + q2;
        const float* g3 = x + b3 * ld + kbase + q3;
        if (cg) { pf0 = __ldcg((const float4*)g0); pf1 = __ldcg((const float4*)g1);
                  pf2 = __ldcg((const float4*)g2); pf3 = __ldcg((const float4*)g3); }
        else    { pf0 = __ldg((const float4*)g0);  pf1 = __ldg((const float4*)g1);
                  pf2 = __ldg((const float4*)g2);  pf3 = __ldg((const float4*)g3); }
    }
    for (int c = 0; c < nch; c++) {
        __syncwarp();                      // prior chunk fully consumed
        *(float4*)(buf + b0 * BUFW + q0) = pf0;
        *(float4*)(buf + b1 * BUFW + q1) = pf1;
        *(float4*)(buf + b2_ * BUFW + q2) = pf2;
        *(float4*)(buf + b3 * BUFW + q3) = pf3;
        if (c < nch - 1) {                 // prefetch next chunk under compute
            const int ko = kbase + (c + 1) * 8;
            const float* g0 = x + b0 * ld + ko + q0;
            const float* g1 = x + b1 * ld + ko + q1;
            const float* g2 = x + b2_ * ld + ko + q2;
            const float* g3 = x + b3 * ld + ko + q3;
            if (cg) { pf0 = __ldcg((const float4*)g0); pf1 = __ldcg((const float4*)g1);
                      pf2 = __ldcg((const float4*)g2); pf3 = __ldcg((const float4*)g3); }
            else    { pf0 = __ldg((const float4*)g0);  pf1 = __ldg((const float4*)g1);
                      pf2 = __ldg((const float4*)g2);  pf3 = __ldg((const float4*)g3); }
        }
        __syncwarp();                      // staged data visible
        const float* wb = Wrow0 + kbase + c * 8;
        #pragma unroll
        for (int kk = 0; kk < 8; kk += 4) {
            float4 wv0 = __ldg((const float4*)(wb + 0 * H_ + kk));
            float4 wv1 = __ldg((const float4*)(wb + 1 * H_ + kk));
            float4 wv2 = __ldg((const float4*)(wb + 2 * H_ + kk));
            float4 wv3 = __ldg((const float4*)(wb + 3 * H_ + kk));
            const float* hb = buf + bq * BUFW + kk;
            #pragma unroll
            for (int m = 0; m < 8; m++) {
                float4 hv = *(const float4*)(hb + m * (8 * BUFW));
                acc[0][m] = fma4(wv0, hv, acc[0][m]);
                acc[1][m] = fma4(wv1, hv, acc[1][m]);
                acc[2][m] = fma4(wv2, hv, acc[2][m]);
                acc[3][m] = fma4(wv3, hv, acc[3][m]);
            }
        }
    }
    __syncwarp();
}

// K=32 term, 16 segments (unmerged): warp takes 2 k columns.
__device__ __forceinline__ void term32w2(
    const float* __restrict__ x, int ld, const float* __restrict__ Wrow0,
    int seg, int lane, int bq, float acc[4][8], float* buf)
{
    const int kbase = seg * 2;
    __syncwarp();
    #pragma unroll
    for (int i = 0; i < 2; i++) {
        int b = lane + (i << 5);
        float2 v = __ldg((const float2*)(x + b * ld + kbase));
        *(float2*)(buf + b * BUFW) = v;
    }
    __syncwarp();
    float2 w0 = __ldg((const float2*)(Wrow0 + 0 * DIN + kbase));
    float2 w1 = __ldg((const float2*)(Wrow0 + 1 * DIN + kbase));
    float2 w2 = __ldg((const float2*)(Wrow0 + 2 * DIN + kbase));
    float2 w3 = __ldg((const float2*)(Wrow0 + 3 * DIN + kbase));
    #pragma unroll
    for (int m = 0; m < 8; m++) {
        float2 hv = *(const float2*)(buf + ((m << 3) + bq) * BUFW);
        acc[0][m] = fmaf(w0.x, hv.x, fmaf(w0.y, hv.y, acc[0][m]));
        acc[1][m] = fmaf(w1.x, hv.x, fmaf(w1.y, hv.y, acc[1][m]));
        acc[2][m] = fmaf(w2.x, hv.x, fmaf(w2.y, hv.y, acc[2][m]));
        acc[3][m] = fmaf(w3.x, hv.x, fmaf(w3.y, hv.y, acc[3][m]));
    }
    __syncwarp();
}

// K=32 term, 8 segments (merged encoder): warp takes 4 k columns.
__device__ __forceinline__ void term32w4(
    const float* __restrict__ x, int ld, const float* __restrict__ Wrow0,
    int seg, int lane, int bq, float acc[4][8], float* buf)
{
    const int kbase = seg * 4;
    __syncwarp();
    #pragma unroll
    for (int i = 0; i < 2; i++) {
        int b = lane + (i << 5);
        float4 v = __ldg((const float4*)(x + b * ld + kbase));
        *(float4*)(buf + b * BUFW) = v;
    }
    __syncwarp();
    float4 w0 = __ldg((const float4*)(Wrow0 + 0 * DIN + kbase));
    float4 w1 = __ldg((const float4*)(Wrow0 + 1 * DIN + kbase));
    float4 w2 = __ldg((const float4*)(Wrow0 + 2 * DIN + kbase));
    float4 w3 = __ldg((const float4*)(Wrow0 + 3 * DIN + kbase));
    #pragma unroll
    for (int m = 0; m < 8; m++) {
        float4 hv = *(const float4*)(buf + ((m << 3) + bq) * BUFW);
        acc[0][m] = fma4(w0, hv, acc[0][m]);
        acc[1][m] = fma4(w1, hv, acc[1][m]);
        acc[2][m] = fma4(w2, hv, acc[2][m]);
        acc[3][m] = fma4(w3, hv, acc[3][m]);
    }
    __syncwarp();
}

// ---- unmerged LSTM phase (decoder + encoder prologue/epilogue) ----
// 16 warps, 32-k slice each. Term A: KA in {0,32,512}; term B: K=512 (.cg).
__device__ __forceinline__ void lstm_phase(
    const float* xA, int ldA, const float* __restrict__ WA, int KA, bool cgA,
    const float* xB, const float* __restrict__ WB,
    const float* __restrict__ bih, const float* __restrict__ bhh,
    const float* __restrict__ b2,
    float* __restrict__ cst, float* __restrict__ hout, float* smem)
{
    const int tid  = threadIdx.x;
    const int w    = tid >> 5, lane = tid & 31;
    const int gate = lane >> 3, bq = lane & 7;
    float* buf = smem + w * BUFSZ;
    float* red = smem + REDBASE;

    float acc[4][8];
    #pragma unroll
    for (int r = 0; r < 4; r++)
        #pragma unroll
        for (int m = 0; m < 8; m++) acc[r][m] = 0.0f;

    const size_t rowbase = (size_t)((gate << 9) + (blockIdx.x << 2));
    if (KA == 512)     term512(xA, ldA, WA + rowbase * H_, cgA, w * 32, 4, lane, bq, acc, buf);
    else if (KA == 32) term32w2(xA, ldA, WA + rowbase * DIN, w, lane, bq, acc, buf);
    term512(xB, H_, WB + rowbase * H_, true, w * 32, 4, lane, bq, acc, buf);

    #pragma unroll
    for (int rr = 0; rr < 4; rr++)
        #pragma unroll
        for (int m = 0; m < 8; m++)
            red[((gate << 2) + rr) * RROW + (w << 6) + (m << 3) + bq] = acc[rr][m];
    __syncthreads();

    if (tid < 256) {
        const int u = tid & 3, b = tid >> 2;
        const int ug = (blockIdx.x << 2) + u;
        float g4v[4];
        #pragma unroll
        for (int g = 0; g < 4; g++) {
            float s = 0.0f;
            #pragma unroll
            for (int s16 = 0; s16 < 16; s16++)
                s += red[((g << 2) + u) * RROW + (s16 << 6) + b];
            int r = (g << 9) + ug;
            s += __ldg(bih + r) + __ldg(bhh + r);
            if (b2) s += __ldg(b2 + r);
            g4v[g] = s;
        }
        const int idx = (b << 9) + ug;
        float cp = __ldcg(cst + idx);
        float cn = sigm(g4v[1]) * cp + sigm(g4v[0]) * tanhf(g4v[2]);
        __stcg(cst + idx, cn);
        __stcg(hout + idx, sigm(g4v[3]) * tanhf(cn));
    }
}

// ---- merged encoder phase p (1..1023): computes L1(p-1) AND L0(p) ----
// Warps 0-7: L0 tile (src(p) + h0(p-1)@eWhh0), 64-k slices.
// Warps 8-15: L1 tile (h0(p-1)@eWih1 + h1(p-2)@eWhh1), 64-k slices.
__device__ __forceinline__ void enc_merged(const P& p, int t, float* smem)
{
    const int tid  = threadIdx.x;
    const int w    = tid >> 5, lane = tid & 31;
    const int grp  = w >> 3, seg = w & 7;
    const int gate = lane >> 3, bq = lane & 7;
    float* buf = smem + w * BUFSZ;
    float* red = smem + REDBASE;

    float acc[4][8];
    #pragma unroll
    for (int r = 0; r < 4; r++)
        #pragma unroll
        for (int m = 0; m < 8; m++) acc[r][m] = 0.0f;

    const size_t rowbase = (size_t)((gate << 9) + (blockIdx.x << 2));
    const float* h0prev = gH0[(t - 1) & 1];     // h0(t-1)
    if (grp == 0) {
        term32w4(p.src + t * DIN, SLEN * DIN, p.eWih0 + rowbase * DIN,
                 seg, lane, bq, acc, buf);
        term512(h0prev, H_, p.eWhh0 + rowbase * H_, true, seg * 64, 8, lane, bq, acc, buf);
    } else {
        const float* h1prev2 = gH1[t & 1];      // h1(t-2) lives in buf t&1
        term512(h0prev,  H_, p.eWih1 + rowbase * H_, true, seg * 64, 8, lane, bq, acc, buf);
        term512(h1prev2, H_, p.eWhh1 + rowbase * H_, true, seg * 64, 8, lane, bq, acc, buf);
    }

    #pragma unroll
    for (int rr = 0; rr < 4; rr++)
        #pragma unroll
        for (int m = 0; m < 8; m++)
            red[((grp << 4) + (gate << 2) + rr) * RROW2 + (seg << 6) + (m << 3) + bq] = acc[rr][m];
    __syncthreads();

    // finalize: 512 threads, one (layer, b, u) each
    {
        const int L = tid >> 8, rem = tid & 255;
        const int u = rem & 3, b = rem >> 2;
        const int ug = (blockIdx.x << 2) + u;
        const float* bih = L ? p.ebih1 : p.ebih0;
        const float* bhh = L ? p.ebhh1 : p.ebhh0;
        float g4v[4];
        #pragma unroll
        for (int g = 0; g < 4; g++) {
            float s = 0.0f;
            #pragma unroll
            for (int s8 = 0; s8 < 8; s8++)
                s += red[((L << 4) + (g << 2) + u) * RROW2 + (s8 << 6) + b];
            int r = (g << 9) + ug;
            s += __ldg(bih + r) + __ldg(bhh + r);
            g4v[g] = s;
        }
        float* cst  = L ? gC1 : gC0;
        float* hout = L ? gH1[(t - 1) & 1] : gH0[t & 1];
        const int idx = (b << 9) + ug;
        float cp = __ldcg(cst + idx);
        float cn = sigm(g4v[1]) * cp + sigm(g4v[0]) * tanhf(g4v[2]);
        __stcg(cst + idx, cn);
        __stcg(hout + idx, sigm(g4v[3]) * tanhf(cn));
    }
}

// pred(t) = h1 @ out_W.T + out_b -> d_out[:, t, :].
// Spread over ALL CTAs: 64 threads/CTA, 16 outputs/CTA.
__device__ __forceinline__ void do_pred(const P& p, const float* __restrict__ h1, int t)
{
    if (threadIdx.x >= 64) return;
    int g = (blockIdx.x << 6) + threadIdx.x;   // 0..8191
    int oid = g >> 2, part = g & 3;            // 2048 outputs, K split by 4
    int b = oid >> 5, j = oid & 31;
    const float* hr = h1 + (b << 9) + (part << 7);
    const float* wr = p.outW + (j << 9) + (part << 7);
    float s = 0.0f;
    #pragma unroll
    for (int k = 0; k < 128; k += 4) {
        float4 hv = __ldcg((const float4*)(hr + k));
        float4 wv = __ldg ((const float4*)(wr + k));
        s = fmaf(hv.x, wv.x, fmaf(hv.y, wv.y, fmaf(hv.z, wv.z, fmaf(hv.w, wv.w, s))));
    }
    s += __shfl_xor_sync(0xffffffffu, s, 1);
    s += __shfl_xor_sync(0xffffffffu, s, 2);
    if (part == 0)
        p.out[((long)b << 14) + (t << 5) + j] = s + __ldg(p.outB + j);
}

__global__ void __launch_bounds__(NT, 1) seq2seq_kernel(P p)
{
    extern __shared__ float smem[];
    const int gt = blockIdx.x * NT + threadIdx.x;   // 0..65535
    unsigned bgen = g_gen;                          // monotonic barrier epoch

    // ---- zero init: h(-1) lives in buffer 1 ----
    if (gt < B_ * H_) {
        __stcg(&gH0[1][gt], 0.0f);
        __stcg(&gH1[1][gt], 0.0f);
        __stcg(&gC0[gt],    0.0f);
        __stcg(&gC1[gt],    0.0f);
    }
    grid_bar(bgen);

    // ---- precompute M = dec_Wih0 @ out_W, b2 = dec_Wih0 @ out_b ----
    for (int o = gt; o < G4 * H_; o += NB * NT) {
        int rr = o >> 9, hc = o & 511;
        const float* wr = p.dWih0 + rr * DIN;
        const float* oc = p.outW + hc;
        float s = 0.0f;
        #pragma unroll
        for (int j = 0; j < DIN; j++) s = fmaf(__ldg(wr + j), __ldg(oc + j * H_), s);
        __stcg(&gM[o], s);
    }
    if (gt < G4) {
        const float* wr = p.dWih0 + gt * DIN;
        float s = 0.0f;
        #pragma unroll
        for (int j = 0; j < DIN; j++) s = fmaf(__ldg(wr + j), __ldg(p.outB + j), s);
        __stcg(&gB2[gt], s);
    }
    grid_bar(bgen);

    // ---- encoder ----
    // prologue: L0(0)   (reads h0(-1)=zeros in buf 1, writes h0(0) -> buf 0)
    lstm_phase(p.src, SLEN * DIN, p.eWih0, DIN, false,
               gH0[1], p.eWhh0,
               p.ebih0, p.ebhh0, nullptr, gC0, gH0[0], smem);
    grid_bar(bgen);
    // merged main loop: phase t computes L1(t-1) and L0(t)
    for (int t = 1; t < SLEN; t++) {
        enc_merged(p, t, smem);
        grid_bar(bgen);
    }
    // epilogue: L1(1023)  (h0(1023) in buf 1, h1(1022) in buf 0 -> h1(1023) buf 1)
    lstm_phase(gH0[1], H_, p.eWih1, H_, true,
               gH1[0], p.eWhh1,
               p.ebih1, p.ebhh1, nullptr, gC1, gH1[1], smem);
    grid_bar(bgen);

    // ---- decoder: 512 steps x 2 phases (+ pred side job, all CTAs) ----
    // h_dec(t) in buf t&1; h_dec(-1) = encoder finals in buf 1.
    for (int t = 0; t < TLEN; t++) {
        const int rp = (t - 1) & 1, wp = t & 1;
        lstm_phase(t ? gH1[rp] : nullptr, H_, gM, t ? H_ : 0, true,
                   gH0[rp], p.dWhh0,
                   p.dbih0, p.dbhh0, t ? gB2 : nullptr, gC0, gH0[wp], smem);
        if (t > 0) do_pred(p, gH1[rp], t - 1);
        grid_bar(bgen);
        lstm_phase(gH0[wp], H_, p.dWih1, H_, true,
                   gH1[rp], p.dWhh1,
                   p.dbih1, p.dbhh1, nullptr, gC1, gH1[wp], smem);
        grid_bar(bgen);
    }
    // final pred for t = TLEN-1 (h1(511) in buf 1)
    do_pred(p, gH1[1], TLEN - 1);
}

extern "C" void kernel_launch(void* const* d_in, const int* in_sizes, int n_in,
                              void* d_out, int out_size)
{
    const int o = (in_sizes[1] < 100) ? 1 : 0;   // skip target_length scalar if present

    P p;
    p.src   = (const float*)d_in[0];
    p.eWih0 = (const float*)d_in[1 + o];
    p.eWhh0 = (const float*)d_in[2 + o];
    p.ebih0 = (const float*)d_in[3 + o];
    p.ebhh0 = (const float*)d_in[4 + o];
    p.eWih1 = (const float*)d_in[5 + o];
    p.eWhh1 = (const float*)d_in[6 + o];
    p.ebih1 = (const float*)d_in[7 + o];
    p.ebhh1 = (const float*)d_in[8 + o];
    p.dWih0 = (const float*)d_in[9 + o];
    p.dWhh0 = (const float*)d_in[10 + o];
    p.dbih0 = (const float*)d_in[11 + o];
    p.dbhh0 = (const float*)d_in[12 + o];
    p.dWih1 = (const float*)d_in[13 + o];
    p.dWhh1 = (const float*)d_in[14 + o];
    p.dbih1 = (const float*)d_in[15 + o];
    p.dbhh1 = (const float*)d_in[16 + o];
    p.outW  = (const float*)d_in[17 + o];
    p.outB  = (const float*)d_in[18 + o];
    p.out   = (float*)d_out;

    cudaFuncSetAttribute(seq2seq_kernel,
                         cudaFuncAttributeMaxDynamicSharedMemorySize, SMEM_BYTES);
    seq2seq_kernel<<<NB, NT, SMEM_BYTES>>>(p);
}